// round 2
// baseline (speedup 1.0000x reference)
#include <cuda_runtime.h>
#include <cuda_bf16.h>

// GraphSAGEConv: out = mean_agg(x[src] -> dst) @ W_l + b_l + x @ W_r
// N = 100000 nodes, E = 1600000 edges, D_in = D_out = 64.
//
// NOTE: edge_index is int32 (JAX default x64-disabled downcasts int64->int32).
//
// Strategy:
//   1) zero d_out (reused as the float sum accumulator) + cnt scratch
//   2) scatter: 16 threads/edge, float4 gather + red.global.add.v4.f32 (L2 atomics)
//   3) finalize in-place: warp per node, W_l/W_r/b staged in shared memory

#define D 64
#define MAX_NODES (1 << 17)

__device__ float g_cnt[MAX_NODES];

__global__ void zero_kernel(float4* __restrict__ out4, int n4, int n_nodes) {
    int i = blockIdx.x * blockDim.x + threadIdx.x;
    if (i < n4) out4[i] = make_float4(0.f, 0.f, 0.f, 0.f);
    if (i < n_nodes) g_cnt[i] = 0.f;
}

__global__ void scatter_kernel(const float4* __restrict__ x4,
                               const int* __restrict__ src,
                               const int* __restrict__ dst,
                               float* __restrict__ out,
                               int n_edges) {
    int t = blockIdx.x * blockDim.x + threadIdx.x;
    int e = t >> 4;        // edge index
    int l = t & 15;        // 16 lanes cover 64 floats as float4
    if (e >= n_edges) return;

    int s = src[e];
    int d = dst[e];

    float4 v = x4[(long long)s * (D / 4) + l];   // coalesced 256B row read (L2 resident)
    float* p = out + (long long)d * D + l * 4;   // 16B-aligned

    asm volatile("red.global.add.v4.f32 [%0], {%1, %2, %3, %4};"
                 :: "l"(p), "f"(v.x), "f"(v.y), "f"(v.z), "f"(v.w)
                 : "memory");

    if (l == 0) {
        asm volatile("red.global.add.f32 [%0], %1;"
                     :: "l"(&g_cnt[d]), "f"(1.0f)
                     : "memory");
    }
}

// One warp per node. Each lane computes 2 output columns (lane, lane+32).
// W_l, W_r, b_l staged in shared; per-warp mean/x rows staged in shared.
__global__ __launch_bounds__(256) void finalize_kernel(
    const float* __restrict__ x,
    const float* __restrict__ Wl,
    const float* __restrict__ bl,
    const float* __restrict__ Wr,
    float* __restrict__ out,
    int n_nodes) {
    __shared__ float sWl[D * D];
    __shared__ float sWr[D * D];
    __shared__ float sb[D];
    __shared__ float sm[8][D];
    __shared__ float sx[8][D];

    int tid = threadIdx.x;
    for (int i = tid; i < D * D; i += 256) {
        sWl[i] = Wl[i];
        sWr[i] = Wr[i];
    }
    if (tid < D) sb[tid] = bl[tid];
    __syncthreads();

    int warp = tid >> 5;
    int lane = tid & 31;
    int node = blockIdx.x * 8 + warp;
    if (node >= n_nodes) return;

    float inv = 1.0f / fmaxf(g_cnt[node], 1.0f);

    // d_out currently holds the neighbor sums; scale to mean, stage rows.
    sm[warp][lane]      = out[node * D + lane] * inv;
    sm[warp][lane + 32] = out[node * D + lane + 32] * inv;
    sx[warp][lane]      = x[node * D + lane];
    sx[warp][lane + 32] = x[node * D + lane + 32];
    __syncwarp();

    float a0 = sb[lane];
    float a1 = sb[lane + 32];
#pragma unroll
    for (int k = 0; k < D; k++) {
        float mk = sm[warp][k];
        float xk = sx[warp][k];
        a0 = fmaf(mk, sWl[k * D + lane],      a0);
        a0 = fmaf(xk, sWr[k * D + lane],      a0);
        a1 = fmaf(mk, sWl[k * D + lane + 32], a1);
        a1 = fmaf(xk, sWr[k * D + lane + 32], a1);
    }

    out[node * D + lane]      = a0;
    out[node * D + lane + 32] = a1;
}

extern "C" void kernel_launch(void* const* d_in, const int* in_sizes, int n_in,
                              void* d_out, int out_size) {
    const float* x     = (const float*)d_in[0];
    const int*   edges = (const int*)d_in[1];
    const float* Wl    = (const float*)d_in[2];
    const float* bl    = (const float*)d_in[3];
    const float* Wr    = (const float*)d_in[4];
    float*       out   = (float*)d_out;

    int n_nodes = in_sizes[0] / D;      // 100000
    int n_edges = in_sizes[1] / 2;      // 1600000
    const int* src = edges;
    const int* dst = edges + n_edges;

    // 1) zero accumulator + counts
    int n4 = n_nodes * (D / 4);
    int zb = (n4 + 255) / 256;
    zero_kernel<<<zb, 256>>>((float4*)out, n4, n_nodes);

    // 2) edge scatter (16 threads per edge)
    long long total = (long long)n_edges * 16;
    int sb_ = (int)((total + 255) / 256);
    scatter_kernel<<<sb_, 256>>>((const float4*)x, src, dst, out, n_edges);

    // 3) finalize (8 nodes per 256-thread block)
    int fb = (n_nodes + 7) / 8;
    finalize_kernel<<<fb, 256>>>(x, Wl, bl, Wr, out, n_nodes);
}

// round 3
// speedup vs baseline: 1.7472x; 1.7472x over previous
#include <cuda_runtime.h>
#include <cuda_bf16.h>

// GraphSAGEConv: out = mean_agg(x[src] -> dst) @ W_l + b_l + x @ W_r
// N = 100000, E = 1600000, D_in = D_out = 64. edge_index is int32.
//
//   1) zero d_out (sum accumulator) + cnt
//   2) scatter: 16 threads/edge, float4 gather + red.global.add.v4.f32
//   3) finalize: register-blocked GEMM  C = [mean|x](K=128) @ [Wl;Wr] + b, in-place

#define D 64
#define MAX_NODES (1 << 17)

__device__ float g_cnt[MAX_NODES];

__global__ void zero_kernel(float4* __restrict__ out4, int n4, int n_nodes) {
    int i = blockIdx.x * blockDim.x + threadIdx.x;
    if (i < n4) out4[i] = make_float4(0.f, 0.f, 0.f, 0.f);
    if (i < n_nodes) g_cnt[i] = 0.f;
}

__global__ void scatter_kernel(const float4* __restrict__ x4,
                               const int* __restrict__ src,
                               const int* __restrict__ dst,
                               float* __restrict__ out,
                               int n_edges) {
    int t = blockIdx.x * blockDim.x + threadIdx.x;
    int e = t >> 4;
    int l = t & 15;
    if (e >= n_edges) return;

    int s = src[e];
    int d = dst[e];

    float4 v = x4[(long long)s * (D / 4) + l];
    float* p = out + (long long)d * D + l * 4;

    asm volatile("red.global.add.v4.f32 [%0], {%1, %2, %3, %4};"
                 :: "l"(p), "f"(v.x), "f"(v.y), "f"(v.z), "f"(v.w)
                 : "memory");

    if (l == 0) {
        asm volatile("red.global.add.f32 [%0], %1;"
                     :: "l"(&g_cnt[d]), "f"(1.0f)
                     : "memory");
    }
}

// Tiled GEMM finalize. Block: 64 nodes x 64 cols, 256 threads, 4x4 micro-tiles.
// Dynamic smem: Bs[128][64] (Wl;Wr, 32KB) + As[64][128] ([mean|x], 32KB).
__global__ __launch_bounds__(256) void finalize_gemm(
    const float* __restrict__ x,
    const float* __restrict__ Wl,
    const float* __restrict__ bl,
    const float* __restrict__ Wr,
    float* __restrict__ out,
    int n_nodes) {
    extern __shared__ float smem[];
    float* Bs = smem;            // [128][64]  row k<64: Wl[k][:], k>=64: Wr[k-64][:]
    float* As = smem + 128 * 64; // [64][128]  row r: [mean_r (64) | x_r (64)]

    int tid = threadIdx.x;
    int row0 = blockIdx.x * 64;

    // stage weights (linear copy; pitch is exactly 64)
    {
        float4* Bs4 = (float4*)Bs;
        const float4* Wl4 = (const float4*)Wl;
        const float4* Wr4 = (const float4*)Wr;
        for (int i = tid; i < 1024; i += 256) Bs4[i] = Wl4[i];
        for (int i = tid; i < 1024; i += 256) Bs4[1024 + i] = Wr4[i];
    }

    // stage A tile: 64 rows; per row 16 float4 of mean + 16 float4 of x
    for (int i = tid; i < 64 * 16; i += 256) {
        int r = i >> 4;          // local row
        int k4 = i & 15;         // float4 index within half
        int node = row0 + r;
        float4 mv = make_float4(0.f, 0.f, 0.f, 0.f);
        float4 xv = make_float4(0.f, 0.f, 0.f, 0.f);
        if (node < n_nodes) {
            float inv = 1.0f / fmaxf(g_cnt[node], 1.0f);
            float4 sv = ((const float4*)out)[node * 16 + k4];
            mv = make_float4(sv.x * inv, sv.y * inv, sv.z * inv, sv.w * inv);
            xv = ((const float4*)x)[node * 16 + k4];
        }
        float* arow = As + r * 128;
        arow[k4 * 4 + 0] = mv.x; arow[k4 * 4 + 1] = mv.y;
        arow[k4 * 4 + 2] = mv.z; arow[k4 * 4 + 3] = mv.w;
        arow[64 + k4 * 4 + 0] = xv.x; arow[64 + k4 * 4 + 1] = xv.y;
        arow[64 + k4 * 4 + 2] = xv.z; arow[64 + k4 * 4 + 3] = xv.w;
    }
    __syncthreads();

    int tx = tid & 15;           // col group: cols tx*4 .. +3
    int ty = tid >> 4;           // row group: rows ty*4 .. +3

    float4 bv = ((const float4*)bl)[tx];
    float acc[4][4];
#pragma unroll
    for (int i = 0; i < 4; i++) {
        acc[i][0] = bv.x; acc[i][1] = bv.y; acc[i][2] = bv.z; acc[i][3] = bv.w;
    }

#pragma unroll 8
    for (int k = 0; k < 128; k++) {
        float4 b = *(const float4*)&Bs[k * 64 + tx * 4];
        float a0 = As[(ty * 4 + 0) * 128 + k];
        float a1 = As[(ty * 4 + 1) * 128 + k];
        float a2 = As[(ty * 4 + 2) * 128 + k];
        float a3 = As[(ty * 4 + 3) * 128 + k];
        acc[0][0] = fmaf(a0, b.x, acc[0][0]); acc[0][1] = fmaf(a0, b.y, acc[0][1]);
        acc[0][2] = fmaf(a0, b.z, acc[0][2]); acc[0][3] = fmaf(a0, b.w, acc[0][3]);
        acc[1][0] = fmaf(a1, b.x, acc[1][0]); acc[1][1] = fmaf(a1, b.y, acc[1][1]);
        acc[1][2] = fmaf(a1, b.z, acc[1][2]); acc[1][3] = fmaf(a1, b.w, acc[1][3]);
        acc[2][0] = fmaf(a2, b.x, acc[2][0]); acc[2][1] = fmaf(a2, b.y, acc[2][1]);
        acc[2][2] = fmaf(a2, b.z, acc[2][2]); acc[2][3] = fmaf(a2, b.w, acc[2][3]);
        acc[3][0] = fmaf(a3, b.x, acc[3][0]); acc[3][1] = fmaf(a3, b.y, acc[3][1]);
        acc[3][2] = fmaf(a3, b.z, acc[3][2]); acc[3][3] = fmaf(a3, b.w, acc[3][3]);
    }
    __syncthreads();   // all reads of 'out' rows done before in-place writes

#pragma unroll
    for (int i = 0; i < 4; i++) {
        int node = row0 + ty * 4 + i;
        if (node < n_nodes) {
            float4 v = make_float4(acc[i][0], acc[i][1], acc[i][2], acc[i][3]);
            ((float4*)out)[node * 16 + tx] = v;
        }
    }
}

extern "C" void kernel_launch(void* const* d_in, const int* in_sizes, int n_in,
                              void* d_out, int out_size) {
    const float* x     = (const float*)d_in[0];
    const int*   edges = (const int*)d_in[1];
    const float* Wl    = (const float*)d_in[2];
    const float* bl    = (const float*)d_in[3];
    const float* Wr    = (const float*)d_in[4];
    float*       out   = (float*)d_out;

    int n_nodes = in_sizes[0] / D;      // 100000
    int n_edges = in_sizes[1] / 2;      // 1600000
    const int* src = edges;
    const int* dst = edges + n_edges;

    // 1) zero accumulator + counts
    int n4 = n_nodes * (D / 4);
    int zb = (n4 + 255) / 256;
    zero_kernel<<<zb, 256>>>((float4*)out, n4, n_nodes);

    // 2) edge scatter (16 threads per edge)
    long long total = (long long)n_edges * 16;
    int sb_ = (int)((total + 255) / 256);
    scatter_kernel<<<sb_, 256>>>((const float4*)x, src, dst, out, n_edges);

    // 3) finalize GEMM (64 nodes per block, 64KB dynamic smem)
    int smem_bytes = (128 * 64 + 64 * 128) * (int)sizeof(float);   // 65536
    cudaFuncSetAttribute(finalize_gemm,
                         cudaFuncAttributeMaxDynamicSharedMemorySize, smem_bytes);
    int fb = (n_nodes + 63) / 64;
    finalize_gemm<<<fb, 256, smem_bytes>>>(x, Wl, bl, Wr, out, n_nodes);
}

// round 4
// speedup vs baseline: 2.0506x; 1.1737x over previous
#include <cuda_runtime.h>
#include <cuda_bf16.h>

// GraphSAGEConv: out = mean_agg(x[src] -> dst) @ W_l + b_l + x @ W_r
// N = 100000, E = 1600000, D_in = D_out = 64. edge_index is int32.
//
// Pipeline (device-built CSR, no RED on feature rows):
//   1) zero g_deg
//   2) histogram of dst degrees
//   3) exclusive scan -> g_off (3 kernels)
//   4) fill adjacency: slot = atomicAdd(&g_off[d],1); after this pass
//      g_off[d] == exclusive offset of d+1 (cursor-free trick)
//   5) aggregate: warp per node, sum neighbor rows, write MEAN once
//   6) finalize: register-blocked GEMM  C = [mean|x](K=128) @ [Wl;Wr] + b

#define D 64
#define MAX_NODES (1 << 17)
#define MAX_EDGES (1 << 21)
#define SCAN_TILE 1024

__device__ int g_deg[MAX_NODES];
__device__ int g_off[MAX_NODES];
__device__ int g_bsum[256];
__device__ int g_adj[MAX_EDGES];

__global__ void zero_deg(int n_nodes) {
    int i = blockIdx.x * blockDim.x + threadIdx.x;
    if (i < n_nodes) g_deg[i] = 0;
}

__global__ void hist_kernel(const int* __restrict__ dst, int n_edges) {
    int e = blockIdx.x * blockDim.x + threadIdx.x;
    if (e < n_edges) atomicAdd(&g_deg[dst[e]], 1);
}

// per-block scan of 1024 degrees (256 threads x 4), exclusive offsets out
__global__ __launch_bounds__(256) void scan1(int n) {
    __shared__ int ssum[256];
    int tid = threadIdx.x;
    int base = blockIdx.x * SCAN_TILE + tid * 4;
    int v0 = base + 0 < n ? g_deg[base + 0] : 0;
    int v1 = base + 1 < n ? g_deg[base + 1] : 0;
    int v2 = base + 2 < n ? g_deg[base + 2] : 0;
    int v3 = base + 3 < n ? g_deg[base + 3] : 0;
    int tsum = v0 + v1 + v2 + v3;
    ssum[tid] = tsum;
    __syncthreads();
    for (int off = 1; off < 256; off <<= 1) {
        int t = (tid >= off) ? ssum[tid - off] : 0;
        __syncthreads();
        ssum[tid] += t;
        __syncthreads();
    }
    int run = ssum[tid] - tsum;   // exclusive prefix within block
    if (base + 0 < n) g_off[base + 0] = run;           run += v0;
    if (base + 1 < n) g_off[base + 1] = run;           run += v1;
    if (base + 2 < n) g_off[base + 2] = run;           run += v2;
    if (base + 3 < n) g_off[base + 3] = run;
    if (tid == 255) g_bsum[blockIdx.x] = ssum[255];
}

__global__ __launch_bounds__(128) void scan2(int nblocks) {
    __shared__ int s[128];
    int tid = threadIdx.x;
    int v = tid < nblocks ? g_bsum[tid] : 0;
    s[tid] = v;
    __syncthreads();
    for (int off = 1; off < 128; off <<= 1) {
        int t = (tid >= off) ? s[tid - off] : 0;
        __syncthreads();
        s[tid] += t;
        __syncthreads();
    }
    if (tid < nblocks) g_bsum[tid] = s[tid] - v;   // exclusive
}

__global__ void scan3(int n) {
    int i = blockIdx.x * blockDim.x + threadIdx.x;
    if (i < n) g_off[i] += g_bsum[i / SCAN_TILE];
}

__global__ void fill_kernel(const int* __restrict__ src,
                            const int* __restrict__ dst, int n_edges) {
    int e = blockIdx.x * blockDim.x + threadIdx.x;
    if (e >= n_edges) return;
    int slot = atomicAdd(&g_off[dst[e]], 1);
    g_adj[slot] = src[e];
}

// Warp per node: sum neighbor rows, write mean once. After fill,
// g_off[node] == end of node's list; beg == (node ? g_off[node-1] : 0).
__global__ __launch_bounds__(256) void agg_kernel(
    const float2* __restrict__ x2, float* __restrict__ out, int n_nodes) {
    int warp = (blockIdx.x * 256 + threadIdx.x) >> 5;
    int lane = threadIdx.x & 31;
    if (warp >= n_nodes) return;

    int end = g_off[warp];
    int beg = warp ? g_off[warp - 1] : 0;
    int deg = end - beg;

    float2 acc = make_float2(0.f, 0.f);
    int i = beg;
#pragma unroll 1
    for (; i + 4 <= end; i += 4) {
        int s0 = g_adj[i + 0], s1 = g_adj[i + 1];
        int s2 = g_adj[i + 2], s3 = g_adj[i + 3];
        float2 v0 = x2[(long long)s0 * 32 + lane];
        float2 v1 = x2[(long long)s1 * 32 + lane];
        float2 v2 = x2[(long long)s2 * 32 + lane];
        float2 v3 = x2[(long long)s3 * 32 + lane];
        acc.x += (v0.x + v1.x) + (v2.x + v3.x);
        acc.y += (v0.y + v1.y) + (v2.y + v3.y);
    }
    for (; i < end; i++) {
        int s = g_adj[i];
        float2 v = x2[(long long)s * 32 + lane];
        acc.x += v.x;
        acc.y += v.y;
    }

    float inv = 1.0f / fmaxf((float)deg, 1.0f);
    float2* o2 = (float2*)out;
    o2[(long long)warp * 32 + lane] = make_float2(acc.x * inv, acc.y * inv);
}

// Tiled GEMM finalize. Block: 64 nodes x 64 cols, 256 threads, 4x4 micro-tiles.
__global__ __launch_bounds__(256) void finalize_gemm(
    const float* __restrict__ x,
    const float* __restrict__ Wl,
    const float* __restrict__ bl,
    const float* __restrict__ Wr,
    float* __restrict__ out,
    int n_nodes) {
    extern __shared__ float smem[];
    float* Bs = smem;            // [128][64]  k<64: Wl, k>=64: Wr
    float* As = smem + 128 * 64; // [64][128]  [mean | x]

    int tid = threadIdx.x;
    int row0 = blockIdx.x * 64;

    {
        float4* Bs4 = (float4*)Bs;
        const float4* Wl4 = (const float4*)Wl;
        const float4* Wr4 = (const float4*)Wr;
        for (int i = tid; i < 1024; i += 256) Bs4[i] = Wl4[i];
        for (int i = tid; i < 1024; i += 256) Bs4[1024 + i] = Wr4[i];
    }

    for (int i = tid; i < 64 * 16; i += 256) {
        int r = i >> 4;
        int k4 = i & 15;
        int node = row0 + r;
        float4 mv = make_float4(0.f, 0.f, 0.f, 0.f);
        float4 xv = make_float4(0.f, 0.f, 0.f, 0.f);
        if (node < n_nodes) {
            mv = ((const float4*)out)[node * 16 + k4];   // mean (written by agg)
            xv = ((const float4*)x)[node * 16 + k4];
        }
        float* arow = As + r * 128;
        arow[k4 * 4 + 0] = mv.x; arow[k4 * 4 + 1] = mv.y;
        arow[k4 * 4 + 2] = mv.z; arow[k4 * 4 + 3] = mv.w;
        arow[64 + k4 * 4 + 0] = xv.x; arow[64 + k4 * 4 + 1] = xv.y;
        arow[64 + k4 * 4 + 2] = xv.z; arow[64 + k4 * 4 + 3] = xv.w;
    }
    __syncthreads();

    int tx = tid & 15;
    int ty = tid >> 4;

    float4 bv = ((const float4*)bl)[tx];
    float acc[4][4];
#pragma unroll
    for (int i = 0; i < 4; i++) {
        acc[i][0] = bv.x; acc[i][1] = bv.y; acc[i][2] = bv.z; acc[i][3] = bv.w;
    }

#pragma unroll 8
    for (int k = 0; k < 128; k++) {
        float4 b = *(const float4*)&Bs[k * 64 + tx * 4];
        float a0 = As[(ty * 4 + 0) * 128 + k];
        float a1 = As[(ty * 4 + 1) * 128 + k];
        float a2 = As[(ty * 4 + 2) * 128 + k];
        float a3 = As[(ty * 4 + 3) * 128 + k];
        acc[0][0] = fmaf(a0, b.x, acc[0][0]); acc[0][1] = fmaf(a0, b.y, acc[0][1]);
        acc[0][2] = fmaf(a0, b.z, acc[0][2]); acc[0][3] = fmaf(a0, b.w, acc[0][3]);
        acc[1][0] = fmaf(a1, b.x, acc[1][0]); acc[1][1] = fmaf(a1, b.y, acc[1][1]);
        acc[1][2] = fmaf(a1, b.z, acc[1][2]); acc[1][3] = fmaf(a1, b.w, acc[1][3]);
        acc[2][0] = fmaf(a2, b.x, acc[2][0]); acc[2][1] = fmaf(a2, b.y, acc[2][1]);
        acc[2][2] = fmaf(a2, b.z, acc[2][2]); acc[2][3] = fmaf(a2, b.w, acc[2][3]);
        acc[3][0] = fmaf(a3, b.x, acc[3][0]); acc[3][1] = fmaf(a3, b.y, acc[3][1]);
        acc[3][2] = fmaf(a3, b.z, acc[3][2]); acc[3][3] = fmaf(a3, b.w, acc[3][3]);
    }
    __syncthreads();

#pragma unroll
    for (int i = 0; i < 4; i++) {
        int node = row0 + ty * 4 + i;
        if (node < n_nodes) {
            ((float4*)out)[node * 16 + tx] =
                make_float4(acc[i][0], acc[i][1], acc[i][2], acc[i][3]);
        }
    }
}

extern "C" void kernel_launch(void* const* d_in, const int* in_sizes, int n_in,
                              void* d_out, int out_size) {
    const float* x     = (const float*)d_in[0];
    const int*   edges = (const int*)d_in[1];
    const float* Wl    = (const float*)d_in[2];
    const float* bl    = (const float*)d_in[3];
    const float* Wr    = (const float*)d_in[4];
    float*       out   = (float*)d_out;

    int n_nodes = in_sizes[0] / D;      // 100000
    int n_edges = in_sizes[1] / 2;      // 1600000
    const int* src = edges;
    const int* dst = edges + n_edges;

    int nb_nodes = (n_nodes + 255) / 256;
    int nb_edges = (n_edges + 255) / 256;
    int nb_scan  = (n_nodes + SCAN_TILE - 1) / SCAN_TILE;   // 98

    zero_deg<<<nb_nodes, 256>>>(n_nodes);
    hist_kernel<<<nb_edges, 256>>>(dst, n_edges);
    scan1<<<nb_scan, 256>>>(n_nodes);
    scan2<<<1, 128>>>(nb_scan);
    scan3<<<nb_nodes, 256>>>(n_nodes);
    fill_kernel<<<nb_edges, 256>>>(src, dst, n_edges);

    int nb_agg = (n_nodes * 32 + 255) / 256;
    agg_kernel<<<nb_agg, 256>>>((const float2*)x, out, n_nodes);

    int smem_bytes = (128 * 64 + 64 * 128) * (int)sizeof(float);   // 64KB
    cudaFuncSetAttribute(finalize_gemm,
                         cudaFuncAttributeMaxDynamicSharedMemorySize, smem_bytes);
    int fb = (n_nodes + 63) / 64;
    finalize_gemm<<<fb, 256, smem_bytes>>>(x, Wl, bl, Wr, out, n_nodes);
}